// round 2
// baseline (speedup 1.0000x reference)
#include <cuda_runtime.h>
#include <cuda_bf16.h>

// ---------------------------------------------------------------------------
// QuantumLayer: 4 qubits, 2 variational layers, B = 1e6.
//
// z_q(b) = sum_j sign_q(j) * |(W r(b))_j|^2
//   r(b): real 16-vector, tensor product of (cos(x_q/2), sin(x_q/2))
//   W = U * diag((-i)^popcount(k)): fixed complex 16x16 depending only on
//       weights, computed by a 16-thread setup kernel each launch.
//
// Main loop uses Blackwell packed fma.rn.f32x2: accumulator holds (re,im)
// packed in one 64-bit register; W is stored interleaved (re,im) so LDS.128
// yields ready-to-use b64 operands with no pack instructions.
// ---------------------------------------------------------------------------

#define NQ 4
#define DIM 16

// W interleaved: g_W[j*16+k] = (re, im) of W[j][k]. 256 floats = 2 KB.
__device__ float2 g_W[DIM * DIM];

// ---------------------------------------------------------------------------
// Setup kernel: 16 threads; thread k evolves column k of U through the
// variational layers, then folds in the (-i)^popcount(k) encoding phase.
// ---------------------------------------------------------------------------
__global__ void setup_kernel(const float* __restrict__ weights) {
    int k = threadIdx.x;
    if (k >= DIM) return;

    float cr[DIM], ci[DIM];
#pragma unroll
    for (int j = 0; j < DIM; j++) { cr[j] = (j == k) ? 1.0f : 0.0f; ci[j] = 0.0f; }

#pragma unroll
    for (int l = 0; l < 2; l++) {
#pragma unroll
        for (int q = 0; q < NQ; q++) {
            const int mask = 8 >> q;
            float thx = weights[(l * 4 + q) * 3 + 0];
            float thy = weights[(l * 4 + q) * 3 + 1];
            float thz = weights[(l * 4 + q) * 3 + 2];

            // RX = [[c, -i s], [-i s, c]]
            {
                float c = cosf(0.5f * thx), s = sinf(0.5f * thx);
#pragma unroll
                for (int rr = 0; rr < 8; rr++) {
                    int j0 = ((rr & ~(mask - 1)) << 1) | (rr & (mask - 1));
                    int j1 = j0 | mask;
                    float ar0 = cr[j0], ai0 = ci[j0], ar1 = cr[j1], ai1 = ci[j1];
                    cr[j0] = c * ar0 + s * ai1;
                    ci[j0] = c * ai0 - s * ar1;
                    cr[j1] = c * ar1 + s * ai0;
                    ci[j1] = c * ai1 - s * ar0;
                }
            }
            // RY = [[c, -s], [s, c]]
            {
                float c = cosf(0.5f * thy), s = sinf(0.5f * thy);
#pragma unroll
                for (int rr = 0; rr < 8; rr++) {
                    int j0 = ((rr & ~(mask - 1)) << 1) | (rr & (mask - 1));
                    int j1 = j0 | mask;
                    float ar0 = cr[j0], ai0 = ci[j0], ar1 = cr[j1], ai1 = ci[j1];
                    cr[j0] = c * ar0 - s * ar1;
                    ci[j0] = c * ai0 - s * ai1;
                    cr[j1] = s * ar0 + c * ar1;
                    ci[j1] = s * ai0 + c * ai1;
                }
            }
            // RZ = diag(e^{-i t/2}, e^{+i t/2})
            {
                float c = cosf(0.5f * thz), s = sinf(0.5f * thz);
#pragma unroll
                for (int rr = 0; rr < 8; rr++) {
                    int j0 = ((rr & ~(mask - 1)) << 1) | (rr & (mask - 1));
                    int j1 = j0 | mask;
                    float ar0 = cr[j0], ai0 = ci[j0], ar1 = cr[j1], ai1 = ci[j1];
                    cr[j0] = c * ar0 + s * ai0;
                    ci[j0] = c * ai0 - s * ar0;
                    cr[j1] = c * ar1 - s * ai1;
                    ci[j1] = c * ai1 + s * ar1;
                }
            }
        }
        // CNOT ring: (0,1), (1,2), (2,3), (3,0). Swap amplitude rows
        // (j, j^tm) within the control=1 subspace.
#pragma unroll
        for (int e = 0; e < 4; e++) {
            const int ctrl = e;
            const int tgt = (e + 1) & 3;
            const int cm = 8 >> ctrl, tm = 8 >> tgt;
#pragma unroll
            for (int j = 0; j < DIM; j++) {
                if ((j & cm) && !(j & tm)) {
                    int j2 = j ^ tm;
                    float tr = cr[j]; cr[j] = cr[j2]; cr[j2] = tr;
                    float ti = ci[j]; ci[j] = ci[j2]; ci[j2] = ti;
                }
            }
        }
    }

    // Fold encoding phase of this column: (-i)^popcount(k)
    int pc = __popc(k) & 3;
    float pr = (pc == 0) ? 1.0f : (pc == 2) ? -1.0f : 0.0f;
    float pi = (pc == 1) ? -1.0f : (pc == 3) ? 1.0f : 0.0f;

#pragma unroll
    for (int j = 0; j < DIM; j++) {
        g_W[j * DIM + k] = make_float2(cr[j] * pr - ci[j] * pi,
                                       cr[j] * pi + ci[j] * pr);
    }
}

// ---------------------------------------------------------------------------
// Packed f32x2 helpers (Blackwell)
// ---------------------------------------------------------------------------
__device__ __forceinline__ void ffma2(unsigned long long& d,
                                      unsigned long long a,
                                      unsigned long long b) {
    asm("fma.rn.f32x2 %0, %1, %2, %0;" : "+l"(d) : "l"(a), "l"(b));
}

__device__ __forceinline__ unsigned long long pack_dup(float v) {
    unsigned long long out;
    unsigned int u = __float_as_uint(v);
    asm("mov.b64 %0, {%1, %1};" : "=l"(out) : "r"(u));
    return out;
}

__device__ __forceinline__ void unpack2(unsigned long long v, float& lo, float& hi) {
    unsigned int a, b;
    asm("mov.b64 {%0, %1}, %2;" : "=r"(a), "=r"(b) : "l"(v));
    lo = __uint_as_float(a);
    hi = __uint_as_float(b);
}

// ---------------------------------------------------------------------------
// Main kernel: one sample per thread.
// ---------------------------------------------------------------------------
__global__ void __launch_bounds__(256)
qlayer_kernel(const float4* __restrict__ in, float4* __restrict__ out, int nb) {
    // W interleaved (re,im): 16 rows x 8 ulonglong2 (each = 2 packed pairs)
    __shared__ ulonglong2 sW[DIM * 8];

    int t = threadIdx.x;
    if (t < 128) sW[t] = ((const ulonglong2*)g_W)[t];
    __syncthreads();

    int b = blockIdx.x * blockDim.x + t;
    if (b >= nb) return;

    float4 x = in[b];
    float c0, s0, c1, s1, c2, s2, c3, s3;
    __sincosf(0.5f * x.x, &s0, &c0);
    __sincosf(0.5f * x.y, &s1, &c1);
    __sincosf(0.5f * x.z, &s2, &c2);
    __sincosf(0.5f * x.w, &s3, &c3);

    // r[k], k = b0b1b2b3 (qubit 0 = bit 3); packed as (r_k, r_k)
    float a01[4] = { c0 * c1, c0 * s1, s0 * c1, s0 * s1 };
    float a23[4] = { c2 * c3, c2 * s3, s2 * c3, s2 * s3 };
    unsigned long long rp[DIM];
#pragma unroll
    for (int i = 0; i < 4; i++)
#pragma unroll
        for (int j = 0; j < 4; j++)
            rp[(i << 2) | j] = pack_dup(a01[i] * a23[j]);

    float z0 = 0.f, z1 = 0.f, z2 = 0.f, z3 = 0.f;
#pragma unroll
    for (int j = 0; j < DIM; j++) {
        unsigned long long acc = 0ull;  // (re, im) accumulator
#pragma unroll
        for (int c = 0; c < 8; c++) {
            ulonglong2 w = sW[j * 8 + c];       // pairs for k=2c, 2c+1
            ffma2(acc, w.x, rp[2 * c + 0]);
            ffma2(acc, w.y, rp[2 * c + 1]);
        }
        float re, im;
        unpack2(acc, re, im);
        float p = fmaf(re, re, im * im);
        z0 += (j & 8) ? -p : p;
        z1 += (j & 4) ? -p : p;
        z2 += (j & 2) ? -p : p;
        z3 += (j & 1) ? -p : p;
    }

    out[b] = make_float4(z0, z1, z2, z3);
}

// ---------------------------------------------------------------------------
extern "C" void kernel_launch(void* const* d_in, const int* in_sizes, int n_in,
                              void* d_out, int out_size) {
    const float* inputs  = (const float*)d_in[0];
    const float* weights = (const float*)d_in[1];
    if (n_in >= 2 && in_sizes[0] == 24) {  // defensive: identify by size
        weights = (const float*)d_in[0];
        inputs  = (const float*)d_in[1];
    }
    int nb = out_size / 4;  // samples

    setup_kernel<<<1, DIM>>>(weights);
    int threads = 256;
    int blocks = (nb + threads - 1) / threads;
    qlayer_kernel<<<blocks, threads>>>((const float4*)inputs, (float4*)d_out, nb);
}

// round 3
// speedup vs baseline: 1.5797x; 1.5797x over previous
#include <cuda_runtime.h>
#include <cuda_bf16.h>

// ---------------------------------------------------------------------------
// QuantumLayer: 4 qubits, 2 variational layers, B = 1e6.
//
// z_q(b) = r(b)^T A_q r(b),  r = tensor prod of (cos(x_q/2), sin(x_q/2)).
// Half-angle identities turn this into an 81-monomial contraction over the
// per-qubit basis (1, cos x_q, sin x_q):
//     z_q(b) = sum_t T_q[t] * prod_q basis_{t_q}(x_q)
// T[81][4] depends only on weights; computed by a 1-block setup kernel:
//     T_q[t] = (1/16) sum_k (-1)^popc(k & sgnmask(t)) A_q[k, k ^ mixmask(t)]
// Main kernel: 2 samples/thread, factorized contraction with fma.rn.f32x2.
// ---------------------------------------------------------------------------

#define DIM 16

__device__ float4 g_T4[81];   // (T0,T1,T2,T3) per monomial idx = 27t0+9t1+3t2+t3

// ---------------------------------------------------------------------------
// Setup kernel: one block, 256 threads, three phases.
// ---------------------------------------------------------------------------
__global__ void setup_kernel(const float* __restrict__ weights) {
    __shared__ float sWre[DIM][DIM];   // [j][k]
    __shared__ float sWim[DIM][DIM];
    __shared__ float sA[4][256];       // A_q[k*16+k']
    int tid = threadIdx.x;

    // ---- Phase 1: threads 0-15 evolve column k of U, fold encoding phase ----
    if (tid < DIM) {
        int k = tid;
        float cr[DIM], ci[DIM];
#pragma unroll
        for (int j = 0; j < DIM; j++) { cr[j] = (j == k) ? 1.0f : 0.0f; ci[j] = 0.0f; }

#pragma unroll
        for (int l = 0; l < 2; l++) {
#pragma unroll
            for (int q = 0; q < 4; q++) {
                const int mask = 8 >> q;
                float thx = weights[(l * 4 + q) * 3 + 0];
                float thy = weights[(l * 4 + q) * 3 + 1];
                float thz = weights[(l * 4 + q) * 3 + 2];
                // RX
                {
                    float c = cosf(0.5f * thx), s = sinf(0.5f * thx);
#pragma unroll
                    for (int rr = 0; rr < 8; rr++) {
                        int j0 = ((rr & ~(mask - 1)) << 1) | (rr & (mask - 1));
                        int j1 = j0 | mask;
                        float ar0 = cr[j0], ai0 = ci[j0], ar1 = cr[j1], ai1 = ci[j1];
                        cr[j0] = c * ar0 + s * ai1;
                        ci[j0] = c * ai0 - s * ar1;
                        cr[j1] = c * ar1 + s * ai0;
                        ci[j1] = c * ai1 - s * ar0;
                    }
                }
                // RY
                {
                    float c = cosf(0.5f * thy), s = sinf(0.5f * thy);
#pragma unroll
                    for (int rr = 0; rr < 8; rr++) {
                        int j0 = ((rr & ~(mask - 1)) << 1) | (rr & (mask - 1));
                        int j1 = j0 | mask;
                        float ar0 = cr[j0], ai0 = ci[j0], ar1 = cr[j1], ai1 = ci[j1];
                        cr[j0] = c * ar0 - s * ar1;
                        ci[j0] = c * ai0 - s * ai1;
                        cr[j1] = s * ar0 + c * ar1;
                        ci[j1] = s * ai0 + c * ai1;
                    }
                }
                // RZ
                {
                    float c = cosf(0.5f * thz), s = sinf(0.5f * thz);
#pragma unroll
                    for (int rr = 0; rr < 8; rr++) {
                        int j0 = ((rr & ~(mask - 1)) << 1) | (rr & (mask - 1));
                        int j1 = j0 | mask;
                        float ar0 = cr[j0], ai0 = ci[j0], ar1 = cr[j1], ai1 = ci[j1];
                        cr[j0] = c * ar0 + s * ai0;
                        ci[j0] = c * ai0 - s * ar0;
                        cr[j1] = c * ar1 - s * ai1;
                        ci[j1] = c * ai1 + s * ar1;
                    }
                }
            }
            // CNOT ring (0,1),(1,2),(2,3),(3,0): row swaps
#pragma unroll
            for (int e = 0; e < 4; e++) {
                const int cm = 8 >> e, tm = 8 >> ((e + 1) & 3);
#pragma unroll
                for (int j = 0; j < DIM; j++) {
                    if ((j & cm) && !(j & tm)) {
                        int j2 = j ^ tm;
                        float tr = cr[j]; cr[j] = cr[j2]; cr[j2] = tr;
                        float ti = ci[j]; ci[j] = ci[j2]; ci[j2] = ti;
                    }
                }
            }
        }

        // Encoding phase (-i)^popc(k)
        int pc = __popc(k) & 3;
        float pr = (pc == 0) ? 1.0f : (pc == 2) ? -1.0f : 0.0f;
        float pi = (pc == 1) ? -1.0f : (pc == 3) ? 1.0f : 0.0f;
#pragma unroll
        for (int j = 0; j < DIM; j++) {
            sWre[j][k] = cr[j] * pr - ci[j] * pi;
            sWim[j][k] = cr[j] * pi + ci[j] * pr;
        }
    }
    __syncthreads();

    // ---- Phase 2: thread tid = k*16+k' computes A_q[k,k'] ----
    {
        int k = tid >> 4, kp = tid & 15;
        float a0 = 0.f, a1 = 0.f, a2 = 0.f, a3 = 0.f;
#pragma unroll
        for (int j = 0; j < DIM; j++) {
            float p = sWre[j][k] * sWre[j][kp] + sWim[j][k] * sWim[j][kp];
            a0 += (j & 8) ? -p : p;
            a1 += (j & 4) ? -p : p;
            a2 += (j & 2) ? -p : p;
            a3 += (j & 1) ? -p : p;
        }
        sA[0][tid] = a0; sA[1][tid] = a1; sA[2][tid] = a2; sA[3][tid] = a3;
    }
    __syncthreads();

    // ---- Phase 3: threads 0-80 compute T[t] ----
    if (tid < 81) {
        int t0 = tid / 27, t1 = (tid / 9) % 3, t2 = (tid / 3) % 3, t3 = tid % 3;
        int mix = 0, sgn = 0;
        if (t0 == 2) mix |= 8; else if (t0 == 1) sgn |= 8;
        if (t1 == 2) mix |= 4; else if (t1 == 1) sgn |= 4;
        if (t2 == 2) mix |= 2; else if (t2 == 1) sgn |= 2;
        if (t3 == 2) mix |= 1; else if (t3 == 1) sgn |= 1;

        float r0 = 0.f, r1 = 0.f, r2 = 0.f, r3 = 0.f;
#pragma unroll
        for (int k = 0; k < DIM; k++) {
            int idx = k * DIM + (k ^ mix);
            float s = (__popc(k & sgn) & 1) ? -1.0f : 1.0f;
            r0 += s * sA[0][idx];
            r1 += s * sA[1][idx];
            r2 += s * sA[2][idx];
            r3 += s * sA[3][idx];
        }
        const float sc = 1.0f / 16.0f;
        g_T4[tid] = make_float4(r0 * sc, r1 * sc, r2 * sc, r3 * sc);
    }
}

// ---------------------------------------------------------------------------
// Packed f32x2 helpers
// ---------------------------------------------------------------------------
__device__ __forceinline__ void ffma2(unsigned long long& d,
                                      unsigned long long a,
                                      unsigned long long b) {
    asm("fma.rn.f32x2 %0, %1, %2, %0;" : "+l"(d) : "l"(a), "l"(b));
}

__device__ __forceinline__ unsigned long long pack_dup(float v) {
    unsigned long long out;
    unsigned int u = __float_as_uint(v);
    asm("mov.b64 %0, {%1, %1};" : "=l"(out) : "r"(u));
    return out;
}

__device__ __forceinline__ void unpack2(unsigned long long v, float& lo, float& hi) {
    unsigned int a, b;
    asm("mov.b64 {%0, %1}, %2;" : "=r"(a), "=r"(b) : "l"(v));
    lo = __uint_as_float(a);
    hi = __uint_as_float(b);
}

// ---------------------------------------------------------------------------
// Main kernel: 2 samples per thread; factorized 81-monomial contraction.
// sT[a*9+c]: .x = packed (T0,T1), .y = packed (T2,T3).
// ---------------------------------------------------------------------------
__global__ void __launch_bounds__(128)
qlayer_kernel(const float4* __restrict__ in, float4* __restrict__ out, int nb) {
    __shared__ ulonglong2 sT[81];
    int t = threadIdx.x;
    if (t < 81) sT[t] = ((const ulonglong2*)g_T4)[t];
    __syncthreads();

    int p = blockIdx.x * blockDim.x + t;   // pair index
    int b0 = 2 * p;
    if (b0 >= nb) return;
    bool hasB = (b0 + 1) < nb;

    float4 xA = in[b0];
    float4 xB = hasB ? in[b0 + 1] : xA;

    float cA0, sA0, cA1, sA1, cA2, sA2, cA3, sA3;
    __sincosf(xA.x, &sA0, &cA0);
    __sincosf(xA.y, &sA1, &cA1);
    __sincosf(xA.z, &sA2, &cA2);
    __sincosf(xA.w, &sA3, &cA3);
    float cB0, sB0, cB1, sB1, cB2, sB2, cB3, sB3;
    __sincosf(xB.x, &sB0, &cB0);
    __sincosf(xB.y, &sB1, &cB1);
    __sincosf(xB.z, &sB2, &cB2);
    __sincosf(xB.w, &sB3, &cB3);

    // ab[a], a = 3*t0 + t1 over basis (1, c, s) of qubits 0,1 (scalar)
    float abA[9] = { 1.f, cA1, sA1, cA0, cA0 * cA1, cA0 * sA1, sA0, sA0 * cA1, sA0 * sA1 };
    float abB[9] = { 1.f, cB1, sB1, cB0, cB0 * cB1, cB0 * sB1, sB0, sB0 * cB1, sB0 * sB1 };
    // cd[c], c = 3*t2 + t3, qubits 2,3 (packed dup — inner ffma2 operand)
    float cdAs[9] = { 1.f, cA3, sA3, cA2, cA2 * cA3, cA2 * sA3, sA2, sA2 * cA3, sA2 * sA3 };
    float cdBs[9] = { 1.f, cB3, sB3, cB2, cB2 * cB3, cB2 * sB3, sB2, sB2 * cB3, sB2 * sB3 };
    unsigned long long cdA[9], cdB[9];
#pragma unroll
    for (int c = 0; c < 9; c++) { cdA[c] = pack_dup(cdAs[c]); cdB[c] = pack_dup(cdBs[c]); }

    unsigned long long zA01 = 0ull, zA23 = 0ull, zB01 = 0ull, zB23 = 0ull;
#pragma unroll
    for (int a = 0; a < 9; a++) {
        unsigned long long vA01 = 0ull, vA23 = 0ull, vB01 = 0ull, vB23 = 0ull;
#pragma unroll
        for (int c = 0; c < 9; c++) {
            ulonglong2 w = sT[a * 9 + c];
            ffma2(vA01, w.x, cdA[c]);
            ffma2(vA23, w.y, cdA[c]);
            ffma2(vB01, w.x, cdB[c]);
            ffma2(vB23, w.y, cdB[c]);
        }
        unsigned long long aa = pack_dup(abA[a]);
        unsigned long long bb = pack_dup(abB[a]);
        ffma2(zA01, aa, vA01);
        ffma2(zA23, aa, vA23);
        ffma2(zB01, bb, vB01);
        ffma2(zB23, bb, vB23);
    }

    float z0, z1, z2, z3;
    unpack2(zA01, z0, z1);
    unpack2(zA23, z2, z3);
    out[b0] = make_float4(z0, z1, z2, z3);
    if (hasB) {
        unpack2(zB01, z0, z1);
        unpack2(zB23, z2, z3);
        out[b0 + 1] = make_float4(z0, z1, z2, z3);
    }
}

// ---------------------------------------------------------------------------
extern "C" void kernel_launch(void* const* d_in, const int* in_sizes, int n_in,
                              void* d_out, int out_size) {
    const float* inputs  = (const float*)d_in[0];
    const float* weights = (const float*)d_in[1];
    if (n_in >= 2 && in_sizes[0] == 24) {  // defensive: identify by size
        weights = (const float*)d_in[0];
        inputs  = (const float*)d_in[1];
    }
    int nb = out_size / 4;  // samples

    setup_kernel<<<1, 256>>>(weights);
    int pairs = (nb + 1) / 2;
    int threads = 128;
    int blocks = (pairs + threads - 1) / threads;
    qlayer_kernel<<<blocks, threads>>>((const float4*)inputs, (float4*)d_out, nb);
}